// round 8
// baseline (speedup 1.0000x reference)
#include <cuda_runtime.h>
#include <cuda_fp16.h>
#include <cstdint>

#define NUM_USERS 100000
#define NUM_ITEMS 50000
#define N_NODES   150000
#define EMB       64
#define BATCH     16384
#define NNZ_MAX   2400000
#define NB_SCAN   ((N_NODES + 255) / 256)
#define ROWS_PER_BLOCK 32
#define EDGE_CAP  768           // int2 staging cap per block (6 KB smem)

// ---------------- scratch (static device allocations; no cudaMalloc) --------
__device__ float   g_feat0[N_NODES * EMB];
__device__ float   g_feat1[N_NODES * EMB];
__device__ float   g_feat2[N_NODES * EMB];
__device__ __half2 g_xh0[N_NODES * 32];   // permuted fp16 copy of feat0
__device__ __half2 g_xh1[N_NODES * 32];   // permuted fp16 copy of feat1
__device__ int     g_cnt[N_NODES];
__device__ int     g_rowptr[N_NODES + 1];
__device__ int     g_cursor[N_NODES];
__device__ int     g_part[NB_SCAN];
__device__ int     g_partscan[NB_SCAN];
__device__ int2    g_edges[NNZ_MAX];      // sorted-by-row (col, val_bits)

// ---------------- kernel: feat0 = concat(uEmb, iEmb); xh0 = fp16 perm -------
// thread = (node, lane-pair l): reads elements l and l+32 of the node's row.
__global__ void init_feat_kernel(const float* __restrict__ uEmb,
                                 const float* __restrict__ iEmb) {
    int idx = blockIdx.x * blockDim.x + threadIdx.x;   // over N_NODES*32
    if (idx >= N_NODES * 32) return;
    int node = idx >> 5;
    int l    = idx & 31;
    const float* src = (node < NUM_USERS)
                     ? (uEmb + (size_t)node * 64)
                     : (iEmb + (size_t)(node - NUM_USERS) * 64);
    float a = src[l];
    float b = src[l + 32];
    g_feat0[(size_t)node * 64 + l]      = a;
    g_feat0[(size_t)node * 64 + l + 32] = b;
    g_xh0[idx] = __floats2half2_rn(a, b);
}

// ---------------- CSR build: histogram + scan + scatter ---------------------
__global__ void hist_kernel(const int* __restrict__ rows, int nnz) {
    int e = blockIdx.x * 256 + threadIdx.x;
    if (e < nnz) atomicAdd(&g_cnt[rows[e]], 1);
}

__global__ void scan1_kernel() {
    __shared__ int sm[256];
    int t = threadIdx.x;
    int i = blockIdx.x * 256 + t;
    int c = (i < N_NODES) ? g_cnt[i] : 0;
    sm[t] = c;
    __syncthreads();
    #pragma unroll
    for (int off = 1; off < 256; off <<= 1) {
        int v = (t >= off) ? sm[t - off] : 0;
        __syncthreads();
        sm[t] += v;
        __syncthreads();
    }
    if (i < N_NODES) g_rowptr[i] = sm[t] - c;      // block-local exclusive
    if (t == 255) g_part[blockIdx.x] = sm[255];    // block total
}

__global__ void scan2_kernel() {
    __shared__ int sm[1024];
    int t = threadIdx.x;
    int c = (t < NB_SCAN) ? g_part[t] : 0;
    sm[t] = c;
    __syncthreads();
    #pragma unroll
    for (int off = 1; off < 1024; off <<= 1) {
        int v = (t >= off) ? sm[t - off] : 0;
        __syncthreads();
        sm[t] += v;
        __syncthreads();
    }
    if (t < NB_SCAN) g_partscan[t] = sm[t] - c;    // exclusive
}

__global__ void scan3_kernel(int nnz) {
    int t = threadIdx.x;
    int i = blockIdx.x * 256 + t;
    if (i < N_NODES) {
        int v = g_rowptr[i] + g_partscan[blockIdx.x];
        g_rowptr[i] = v;
        g_cursor[i] = v;
    }
    if (i == 0) g_rowptr[N_NODES] = nnz;
}

__global__ void scatter_kernel(const int*   __restrict__ rows,
                               const int*   __restrict__ cols,
                               const float* __restrict__ vals, int nnz) {
    int e = blockIdx.x * 256 + threadIdx.x;
    if (e >= nnz) return;
    int r = rows[e];
    int pos = atomicAdd(&g_cursor[r], 1);
    g_edges[pos] = make_int2(cols[e], __float_as_int(vals[e]));
}

// ---------------- fused layer: feat_out = relu((L@x + x) @ W + b) -----------
// Gathers use the permuted fp16 copy (one half2 = 4B per lane per edge =
// 128B/warp, ONE L2 request). Self-loop + accumulation + GEMM stay fp32.
// Block stages its CSR edge segment in smem; warp = 4 rows; 8-edge batches.
__global__ __launch_bounds__(256)
void spmm_gemm_kernel(const float*   __restrict__ xf,   // fp32 features (self loop)
                      const __half2* __restrict__ xh,   // permuted fp16 copy
                      const float*   __restrict__ W,
                      const float*   __restrict__ b,
                      float*   __restrict__ out,        // fp32 out
                      __half2* __restrict__ outh,       // permuted fp16 out (or null)
                      int nrows) {
    __shared__ float2 sW[64 * 32];    // sW[k*32+j] = (W[k][j], W[k][j+32])
    __shared__ float  sb[64];
    __shared__ int2   sE[EDGE_CAP];
    int tid = threadIdx.x;
    #pragma unroll
    for (int i = tid; i < 2048; i += 256) {
        int k = i >> 5, j = i & 31;
        sW[i] = make_float2(W[k * 64 + j], W[k * 64 + j + 32]);
    }
    if (tid < 64) sb[tid] = b[tid];

    int r_base = blockIdx.x * ROWS_PER_BLOCK;
    int r_end  = min(r_base + ROWS_PER_BLOCK, nrows);
    int blk_s  = g_rowptr[r_base];
    int blk_e  = g_rowptr[r_end];
    int stage  = min(blk_e - blk_s, EDGE_CAP);
    for (int i = tid; i < stage; i += 256) sE[i] = g_edges[blk_s + i];
    __syncthreads();

    int lane = tid & 31;
    int warp = tid >> 5;
    int r0 = r_base + warp * 4;

    float acc0[4], acc1[4];
    #pragma unroll
    for (int rr = 0; rr < 4; rr++) {
        int row = r0 + rr;
        if (row >= nrows) { acc0[rr] = 0.f; acc1[rr] = 0.f; continue; }
        const float* xr = xf + (size_t)row * 64;
        float a0 = xr[lane], a1 = xr[lane + 32];           // self loop (fp32)
        int s = g_rowptr[row] - blk_s, e = g_rowptr[row + 1] - blk_s;
        int i = s;
        for (; i + 8 <= e; i += 8) {
            int2 c[8];
            #pragma unroll
            for (int q = 0; q < 8; q++)
                c[q] = (i + q < EDGE_CAP) ? sE[i + q] : g_edges[blk_s + i + q];
            float2 f[8];
            #pragma unroll
            for (int q = 0; q < 8; q++)
                f[q] = __half22float2(xh[(size_t)c[q].x * 32 + lane]);
            #pragma unroll
            for (int q = 0; q < 8; q++) {
                float v = __int_as_float(c[q].y);
                a0 += v * f[q].x;  a1 += v * f[q].y;
            }
        }
        for (; i < e; i++) {
            int2 cc = (i < EDGE_CAP) ? sE[i] : g_edges[blk_s + i];
            float v = __int_as_float(cc.y);
            float2 fv = __half22float2(xh[(size_t)cc.x * 32 + lane]);
            a0 += v * fv.x;
            a1 += v * fv.y;
        }
        acc0[rr] = a0; acc1[rr] = a1;
    }

    // GEMM epilogue: out[c] = relu(b[c] + sum_k h[k] * W[k][c])
    float o0[4], o1[4];
    #pragma unroll
    for (int rr = 0; rr < 4; rr++) { o0[rr] = sb[lane]; o1[rr] = sb[lane + 32]; }
    #pragma unroll
    for (int k = 0; k < 32; k++) {
        float2 w = sW[k * 32 + lane];
        #pragma unroll
        for (int rr = 0; rr < 4; rr++) {
            float hk = __shfl_sync(0xffffffffu, acc0[rr], k);
            o0[rr] += hk * w.x;  o1[rr] += hk * w.y;
        }
    }
    #pragma unroll
    for (int k = 0; k < 32; k++) {
        float2 w = sW[(k + 32) * 32 + lane];
        #pragma unroll
        for (int rr = 0; rr < 4; rr++) {
            float hk = __shfl_sync(0xffffffffu, acc1[rr], k);
            o0[rr] += hk * w.x;  o1[rr] += hk * w.y;
        }
    }
    #pragma unroll
    for (int rr = 0; rr < 4; rr++) {
        int row = r0 + rr;
        if (row >= nrows) break;
        float r0v = fmaxf(o0[rr], 0.f);
        float r1v = fmaxf(o1[rr], 0.f);
        float* op = out + (size_t)row * 64;
        op[lane]      = r0v;
        op[lane + 32] = r1v;
        if (outh) outh[(size_t)row * 32 + lane] = __floats2half2_rn(r0v, r1v);
    }
}

// ---------------- fused gather + 3-layer MLP --------------------------------
__global__ __launch_bounds__(256)
void mlp_fused_kernel(const int*   __restrict__ userIdx,
                      const int*   __restrict__ itemIdx,
                      const float* __restrict__ W1, const float* __restrict__ b1,
                      const float* __restrict__ W2, const float* __restrict__ b2,
                      const float* __restrict__ W3, const float* __restrict__ b3,
                      float* __restrict__ out) {
    __shared__ float2 sW[64 * 32];    // current W1 segment, paired cols
    __shared__ float  sW2[64 * 32];
    __shared__ float  sb2[32], sW3[32];
    __shared__ float  sb3;

    int tid = threadIdx.x, lane = tid & 31, warp = tid >> 5;
    #pragma unroll
    for (int i = tid; i < 2048; i += 256) sW2[i] = W2[i];
    if (tid < 32) { sb2[tid] = b2[tid]; sW3[tid] = W3[tid]; }
    if (tid == 0) sb3 = b3[0];

    int base = blockIdx.x * 64 + warp * 8;
    int unode[8], inode[8];
    #pragma unroll
    for (int r = 0; r < 8; r++) {
        unode[r] = __ldg(userIdx + base + r);
        inode[r] = __ldg(itemIdx + base + r) + NUM_USERS;
    }

    float bb0 = __ldg(b1 + lane), bb1 = __ldg(b1 + lane + 32);
    float acc0[8], acc1[8];
    #pragma unroll
    for (int r = 0; r < 8; r++) { acc0[r] = bb0; acc1[r] = bb1; }

    #pragma unroll
    for (int kk = 0; kk < 6; kk++) {
        __syncthreads();
        #pragma unroll
        for (int i = tid; i < 2048; i += 256) {
            int k = i >> 5, j = i & 31;
            sW[i] = make_float2(W1[(kk * 64 + k) * 64 + j],
                                W1[(kk * 64 + k) * 64 + j + 32]);
        }
        __syncthreads();

        int seg = (kk < 3) ? kk : kk - 3;
        const float* src = (seg == 0) ? g_feat0 : (seg == 1) ? g_feat1 : g_feat2;

        float a0[8], a1[8];
        #pragma unroll
        for (int r = 0; r < 8; r++) {
            int node = (kk < 3) ? unode[r] : inode[r];
            const float* er = src + (size_t)node * 64;
            a0[r] = er[lane]; a1[r] = er[lane + 32];
        }
        #pragma unroll
        for (int k = 0; k < 32; k++) {
            float2 w = sW[k * 32 + lane];
            #pragma unroll
            for (int r = 0; r < 8; r++) {
                float hk = __shfl_sync(0xffffffffu, a0[r], k);
                acc0[r] += hk * w.x;  acc1[r] += hk * w.y;
            }
        }
        #pragma unroll
        for (int k = 0; k < 32; k++) {
            float2 w = sW[(k + 32) * 32 + lane];
            #pragma unroll
            for (int r = 0; r < 8; r++) {
                float hk = __shfl_sync(0xffffffffu, a1[r], k);
                acc0[r] += hk * w.x;  acc1[r] += hk * w.y;
            }
        }
    }

    // stages 2+3, in-warp
    #pragma unroll
    for (int r = 0; r < 8; r++) {
        float m0  = fmaxf(acc0[r], 0.f);
        float m1v = fmaxf(acc1[r], 0.f);
        float acc = sb2[lane];                 // lane = output col (0..31)
        #pragma unroll
        for (int k = 0; k < 32; k++) {
            float hk = __shfl_sync(0xffffffffu, m0, k);
            acc += hk * sW2[k * 32 + lane];
        }
        #pragma unroll
        for (int k = 0; k < 32; k++) {
            float hk = __shfl_sync(0xffffffffu, m1v, k);
            acc += hk * sW2[(k + 32) * 32 + lane];
        }
        float p = acc * sW3[lane];             // no ReLU after W2 (matches ref)
        #pragma unroll
        for (int off = 16; off > 0; off >>= 1)
            p += __shfl_xor_sync(0xffffffffu, p, off);
        if (lane == 0) out[base + r] = p + sb3;
    }
}

// ---------------- launch ----------------------------------------------------
extern "C" void kernel_launch(void* const* d_in, const int* in_sizes, int n_in,
                              void* d_out, int out_size) {
    const int*   userIdx = (const int*)  d_in[0];
    const int*   itemIdx = (const int*)  d_in[1];
    const int*   lapRows = (const int*)  d_in[2];
    const int*   lapCols = (const int*)  d_in[3];
    const float* lapVals = (const float*)d_in[4];
    const float* uEmb    = (const float*)d_in[5];
    const float* iEmb    = (const float*)d_in[6];
    const float* gW0     = (const float*)d_in[7];
    const float* gb0     = (const float*)d_in[8];
    const float* gW1     = (const float*)d_in[9];
    const float* gb1     = (const float*)d_in[10];
    const float* W1      = (const float*)d_in[11];
    const float* b1      = (const float*)d_in[12];
    const float* W2      = (const float*)d_in[13];
    const float* b2      = (const float*)d_in[14];
    const float* W3      = (const float*)d_in[15];
    const float* b3      = (const float*)d_in[16];
    float* out = (float*)d_out;

    const int nnz = in_sizes[2];

    float   *feat0, *feat1, *feat2;
    __half2 *xh0, *xh1;
    int     *cnt;
    cudaGetSymbolAddress((void**)&feat0, g_feat0);
    cudaGetSymbolAddress((void**)&feat1, g_feat1);
    cudaGetSymbolAddress((void**)&feat2, g_feat2);
    cudaGetSymbolAddress((void**)&xh0,   g_xh0);
    cudaGetSymbolAddress((void**)&xh1,   g_xh1);
    cudaGetSymbolAddress((void**)&cnt,   g_cnt);

    // 1. feat0 = concat(uEmb, iEmb) + permuted fp16 copy
    init_feat_kernel<<<(N_NODES * 32 + 255) / 256, 256>>>(uEmb, iEmb);

    // 2. build CSR (memset -> histogram -> scan -> scatter)
    const int eb = (nnz + 255) / 256;
    cudaMemsetAsync(cnt, 0, N_NODES * sizeof(int));
    hist_kernel<<<eb, 256>>>(lapRows, nnz);
    scan1_kernel<<<NB_SCAN, 256>>>();
    scan2_kernel<<<1, 1024>>>();
    scan3_kernel<<<NB_SCAN, 256>>>(nnz);
    scatter_kernel<<<eb, 256>>>(lapRows, lapCols, lapVals, nnz);

    // 3. fused layers: feat_{k+1} = relu((L @ feat_k + feat_k) @ W + b)
    const int lb = (N_NODES + ROWS_PER_BLOCK - 1) / ROWS_PER_BLOCK;
    spmm_gemm_kernel<<<lb, 256>>>(feat0, xh0, gW0, gb0, feat1, xh1, N_NODES);
    spmm_gemm_kernel<<<lb, 256>>>(feat1, xh1, gW1, gb1, feat2, nullptr, N_NODES);

    // 4. fused gather + 3-layer MLP
    mlp_fused_kernel<<<BATCH / 64, 256>>>(userIdx, itemIdx,
                                          W1, b1, W2, b2, W3, b3, out);
}

// round 9
// speedup vs baseline: 1.0222x; 1.0222x over previous
#include <cuda_runtime.h>
#include <cstdint>

#define NUM_USERS 100000
#define NUM_ITEMS 50000
#define N_NODES   150000
#define EMB       64
#define BATCH     16384
#define NNZ_MAX   2400000
#define NB_SCAN   ((N_NODES + 255) / 256)
#define ROWS_PER_BLOCK 32
#define EDGE_CAP  768           // int2 staging cap per block (6 KB smem)

// ---------------- scratch (static device allocations; no cudaMalloc) --------
__device__ float g_feat1[N_NODES * EMB];
__device__ float g_feat2[N_NODES * EMB];
__device__ int   g_cnt[N_NODES];
__device__ int   g_rowptr[N_NODES + 1];
__device__ int   g_cursor[N_NODES];
__device__ int   g_part[NB_SCAN];
__device__ int2  g_edges[NNZ_MAX];          // sorted-by-row (col, val_bits)

// Split-pointer node row lookup. For layer 2+, pass u=base, i=base+U*64 and
// this reduces to contiguous addressing for every node.
__device__ __forceinline__ const float* node_row(const float* __restrict__ u,
                                                 const float* __restrict__ i,
                                                 int node) {
    return (node < NUM_USERS) ? (u + (size_t)node * EMB)
                              : (i + (size_t)(node - NUM_USERS) * EMB);
}

// ---------------- CSR build: histogram + scan + scatter ---------------------
__global__ void hist_kernel(const int* __restrict__ rows, int nnz) {
    int e = blockIdx.x * 256 + threadIdx.x;
    if (e < nnz) atomicAdd(&g_cnt[rows[e]], 1);
}

__global__ void scan1_kernel() {
    __shared__ int sm[256];
    int t = threadIdx.x;
    int i = blockIdx.x * 256 + t;
    int c = (i < N_NODES) ? g_cnt[i] : 0;
    sm[t] = c;
    __syncthreads();
    #pragma unroll
    for (int off = 1; off < 256; off <<= 1) {
        int v = (t >= off) ? sm[t - off] : 0;
        __syncthreads();
        sm[t] += v;
        __syncthreads();
    }
    if (i < N_NODES) g_rowptr[i] = sm[t] - c;      // block-local exclusive
    if (t == 255) g_part[blockIdx.x] = sm[255];    // block total
}

// scan2+scan3 merged: each block computes its own offset = sum(g_part[0..bid))
__global__ void scan23_kernel(int nnz) {
    __shared__ int red[32];
    int t = threadIdx.x;
    int partial = 0;
    for (int j = t; j < blockIdx.x; j += 256) partial += g_part[j];
    // block reduce
    #pragma unroll
    for (int off = 16; off > 0; off >>= 1)
        partial += __shfl_xor_sync(0xffffffffu, partial, off);
    if ((t & 31) == 0) red[t >> 5] = partial;
    __syncthreads();
    int offset = red[0] + red[1] + red[2] + red[3] +
                 red[4] + red[5] + red[6] + red[7];
    int i = blockIdx.x * 256 + t;
    if (i < N_NODES) {
        int v = g_rowptr[i] + offset;
        g_rowptr[i] = v;
        g_cursor[i] = v;
    }
    if (i == 0) g_rowptr[N_NODES] = nnz;
}

__global__ void scatter_kernel(const int*   __restrict__ rows,
                               const int*   __restrict__ cols,
                               const float* __restrict__ vals, int nnz) {
    int e = blockIdx.x * 256 + threadIdx.x;
    if (e >= nnz) return;
    int r = rows[e];
    int pos = atomicAdd(&g_cursor[r], 1);
    g_edges[pos] = make_int2(cols[e], __float_as_int(vals[e]));
}

// ---------------- fused layer: feat_out = relu((L@x + x) @ W + b) -----------
// x is addressed via (xu, xi) split pointers (layer 1 reads raw embeddings).
// Block stages its contiguous CSR edge segment in smem; warp = 4 rows;
// 8-edge batches; shuffle-GEMM epilogue with float2-packed weights.
__global__ __launch_bounds__(256)
void spmm_gemm_kernel(const float* __restrict__ xu,
                      const float* __restrict__ xi,
                      const float* __restrict__ W,
                      const float* __restrict__ b,
                      float* __restrict__ out, int nrows) {
    __shared__ float2 sW[64 * 32];    // sW[k*32+j] = (W[k][j], W[k][j+32])
    __shared__ float  sb[64];
    __shared__ int2   sE[EDGE_CAP];
    int tid = threadIdx.x;
    #pragma unroll
    for (int i = tid; i < 2048; i += 256) {
        int k = i >> 5, j = i & 31;
        sW[i] = make_float2(W[k * 64 + j], W[k * 64 + j + 32]);
    }
    if (tid < 64) sb[tid] = b[tid];

    int r_base = blockIdx.x * ROWS_PER_BLOCK;
    int r_end  = min(r_base + ROWS_PER_BLOCK, nrows);
    int blk_s  = g_rowptr[r_base];
    int blk_e  = g_rowptr[r_end];
    bool fast  = (blk_e - blk_s) <= EDGE_CAP;
    int stage  = fast ? (blk_e - blk_s) : 0;
    for (int i = tid; i < stage; i += 256) sE[i] = g_edges[blk_s + i];
    __syncthreads();

    int lane = tid & 31;
    int warp = tid >> 5;
    int r0 = r_base + warp * 4;

    float acc0[4], acc1[4];
    #pragma unroll
    for (int rr = 0; rr < 4; rr++) {
        int row = r0 + rr;
        if (row >= nrows) { acc0[rr] = 0.f; acc1[rr] = 0.f; continue; }
        const float* xr = node_row(xu, xi, row);
        float a0 = xr[lane], a1 = xr[lane + 32];           // self loop
        int s = g_rowptr[row] - blk_s, e = g_rowptr[row + 1] - blk_s;
        int i = s;
        if (fast) {
            for (; i + 8 <= e; i += 8) {
                int2 c[8];
                #pragma unroll
                for (int q = 0; q < 8; q++) c[q] = sE[i + q];
                float xs0[8], xs1[8];
                #pragma unroll
                for (int q = 0; q < 8; q++) {
                    const float* xp = node_row(xu, xi, c[q].x);
                    xs0[q] = xp[lane];  xs1[q] = xp[lane + 32];
                }
                #pragma unroll
                for (int q = 0; q < 8; q++) {
                    float v = __int_as_float(c[q].y);
                    a0 += v * xs0[q];  a1 += v * xs1[q];
                }
            }
            for (; i < e; i++) {
                int2 cc = sE[i];
                float v = __int_as_float(cc.y);
                const float* xp = node_row(xu, xi, cc.x);
                a0 += v * xp[lane];
                a1 += v * xp[lane + 32];
            }
        } else {
            for (; i < e; i++) {
                int2 cc = g_edges[blk_s + i];
                float v = __int_as_float(cc.y);
                const float* xp = node_row(xu, xi, cc.x);
                a0 += v * xp[lane];
                a1 += v * xp[lane + 32];
            }
        }
        acc0[rr] = a0; acc1[rr] = a1;
    }

    // GEMM epilogue: out[c] = relu(b[c] + sum_k h[k] * W[k][c])
    float o0[4], o1[4];
    #pragma unroll
    for (int rr = 0; rr < 4; rr++) { o0[rr] = sb[lane]; o1[rr] = sb[lane + 32]; }
    #pragma unroll
    for (int k = 0; k < 32; k++) {
        float2 w = sW[k * 32 + lane];
        #pragma unroll
        for (int rr = 0; rr < 4; rr++) {
            float hk = __shfl_sync(0xffffffffu, acc0[rr], k);
            o0[rr] += hk * w.x;  o1[rr] += hk * w.y;
        }
    }
    #pragma unroll
    for (int k = 0; k < 32; k++) {
        float2 w = sW[(k + 32) * 32 + lane];
        #pragma unroll
        for (int rr = 0; rr < 4; rr++) {
            float hk = __shfl_sync(0xffffffffu, acc1[rr], k);
            o0[rr] += hk * w.x;  o1[rr] += hk * w.y;
        }
    }
    #pragma unroll
    for (int rr = 0; rr < 4; rr++) {
        int row = r0 + rr;
        if (row >= nrows) break;
        float* op = out + (size_t)row * 64;
        op[lane]      = fmaxf(o0[rr], 0.f);
        op[lane + 32] = fmaxf(o1[rr], 0.f);
    }
}

// ---------------- fused gather + 3-layer MLP --------------------------------
__global__ __launch_bounds__(256)
void mlp_fused_kernel(const int*   __restrict__ userIdx,
                      const int*   __restrict__ itemIdx,
                      const float* __restrict__ uEmb,
                      const float* __restrict__ iEmb,
                      const float* __restrict__ W1, const float* __restrict__ b1,
                      const float* __restrict__ W2, const float* __restrict__ b2,
                      const float* __restrict__ W3, const float* __restrict__ b3,
                      float* __restrict__ out) {
    __shared__ float2 sW[64 * 32];    // current W1 segment, paired cols
    __shared__ float  sW2[64 * 32];
    __shared__ float  sb2[32], sW3[32];
    __shared__ float  sb3;

    int tid = threadIdx.x, lane = tid & 31, warp = tid >> 5;
    #pragma unroll
    for (int i = tid; i < 2048; i += 256) sW2[i] = W2[i];
    if (tid < 32) { sb2[tid] = b2[tid]; sW3[tid] = W3[tid]; }
    if (tid == 0) sb3 = b3[0];

    int base = blockIdx.x * 64 + warp * 8;
    int unode[8], inode[8];
    #pragma unroll
    for (int r = 0; r < 8; r++) {
        unode[r] = __ldg(userIdx + base + r);
        inode[r] = __ldg(itemIdx + base + r) + NUM_USERS;
    }

    float bb0 = __ldg(b1 + lane), bb1 = __ldg(b1 + lane + 32);
    float acc0[8], acc1[8];
    #pragma unroll
    for (int r = 0; r < 8; r++) { acc0[r] = bb0; acc1[r] = bb1; }

    #pragma unroll
    for (int kk = 0; kk < 6; kk++) {
        __syncthreads();
        #pragma unroll
        for (int i = tid; i < 2048; i += 256) {
            int k = i >> 5, j = i & 31;
            sW[i] = make_float2(W1[(kk * 64 + k) * 64 + j],
                                W1[(kk * 64 + k) * 64 + j + 32]);
        }
        __syncthreads();

        int seg = (kk < 3) ? kk : kk - 3;

        float a0[8], a1[8];
        #pragma unroll
        for (int r = 0; r < 8; r++) {
            int node = (kk < 3) ? unode[r] : inode[r];
            const float* er;
            if (seg == 0)      er = node_row(uEmb, iEmb, node);
            else if (seg == 1) er = g_feat1 + (size_t)node * 64;
            else               er = g_feat2 + (size_t)node * 64;
            a0[r] = er[lane]; a1[r] = er[lane + 32];
        }
        #pragma unroll
        for (int k = 0; k < 32; k++) {
            float2 w = sW[k * 32 + lane];
            #pragma unroll
            for (int r = 0; r < 8; r++) {
                float hk = __shfl_sync(0xffffffffu, a0[r], k);
                acc0[r] += hk * w.x;  acc1[r] += hk * w.y;
            }
        }
        #pragma unroll
        for (int k = 0; k < 32; k++) {
            float2 w = sW[(k + 32) * 32 + lane];
            #pragma unroll
            for (int r = 0; r < 8; r++) {
                float hk = __shfl_sync(0xffffffffu, a1[r], k);
                acc0[r] += hk * w.x;  acc1[r] += hk * w.y;
            }
        }
    }

    // stages 2+3, in-warp
    #pragma unroll
    for (int r = 0; r < 8; r++) {
        float m0  = fmaxf(acc0[r], 0.f);
        float m1v = fmaxf(acc1[r], 0.f);
        float acc = sb2[lane];                 // lane = output col (0..31)
        #pragma unroll
        for (int k = 0; k < 32; k++) {
            float hk = __shfl_sync(0xffffffffu, m0, k);
            acc += hk * sW2[k * 32 + lane];
        }
        #pragma unroll
        for (int k = 0; k < 32; k++) {
            float hk = __shfl_sync(0xffffffffu, m1v, k);
            acc += hk * sW2[(k + 32) * 32 + lane];
        }
        float p = acc * sW3[lane];             // no ReLU after W2 (matches ref)
        #pragma unroll
        for (int off = 16; off > 0; off >>= 1)
            p += __shfl_xor_sync(0xffffffffu, p, off);
        if (lane == 0) out[base + r] = p + sb3;
    }
}

// ---------------- launch ----------------------------------------------------
extern "C" void kernel_launch(void* const* d_in, const int* in_sizes, int n_in,
                              void* d_out, int out_size) {
    const int*   userIdx = (const int*)  d_in[0];
    const int*   itemIdx = (const int*)  d_in[1];
    const int*   lapRows = (const int*)  d_in[2];
    const int*   lapCols = (const int*)  d_in[3];
    const float* lapVals = (const float*)d_in[4];
    const float* uEmb    = (const float*)d_in[5];
    const float* iEmb    = (const float*)d_in[6];
    const float* gW0     = (const float*)d_in[7];
    const float* gb0     = (const float*)d_in[8];
    const float* gW1     = (const float*)d_in[9];
    const float* gb1     = (const float*)d_in[10];
    const float* W1      = (const float*)d_in[11];
    const float* b1      = (const float*)d_in[12];
    const float* W2      = (const float*)d_in[13];
    const float* b2      = (const float*)d_in[14];
    const float* W3      = (const float*)d_in[15];
    const float* b3      = (const float*)d_in[16];
    float* out = (float*)d_out;

    const int nnz = in_sizes[2];

    float *feat1, *feat2;
    int   *cnt;
    cudaGetSymbolAddress((void**)&feat1, g_feat1);
    cudaGetSymbolAddress((void**)&feat2, g_feat2);
    cudaGetSymbolAddress((void**)&cnt,   g_cnt);

    // 1. build CSR (memset -> histogram -> scan -> scatter)
    const int eb = (nnz + 255) / 256;
    cudaMemsetAsync(cnt, 0, N_NODES * sizeof(int));
    hist_kernel<<<eb, 256>>>(lapRows, nnz);
    scan1_kernel<<<NB_SCAN, 256>>>();
    scan23_kernel<<<NB_SCAN, 256>>>(nnz);
    scatter_kernel<<<eb, 256>>>(lapRows, lapCols, lapVals, nnz);

    // 2. fused layers: feat_{k+1} = relu((L @ feat_k + feat_k) @ W + b)
    //    Layer 1 reads raw embeddings via split pointers (no concat pass).
    //    Layer 2 passes (feat1, feat1 + U*64) -> contiguous addressing.
    const int lb = (N_NODES + ROWS_PER_BLOCK - 1) / ROWS_PER_BLOCK;
    spmm_gemm_kernel<<<lb, 256>>>(uEmb, iEmb, gW0, gb0, feat1, N_NODES);
    spmm_gemm_kernel<<<lb, 256>>>(feat1, feat1 + (size_t)NUM_USERS * EMB,
                                  gW1, gb1, feat2, N_NODES);

    // 3. fused gather + 3-layer MLP (reads embeddings + feat1 + feat2)
    mlp_fused_kernel<<<BATCH / 64, 256>>>(userIdx, itemIdx, uEmb, iEmb,
                                          W1, b1, W2, b2, W3, b3, out);
}